// round 12
// baseline (speedup 1.0000x reference)
#include <cuda_runtime.h>

// ---------------------------------------------------------------------------
// CustomCNN (LeNet-like), batch 8192, sm_100a.
// Channel-collapse identity => conv1(3->6)+tanh+mean+pool -> conv2sum(1->16)
// +tanh+mean+pool -> 25->120 dot -> fc1 -> fc2.
// R11/R12: duplicated-pair SMEM image (zero pack2 in conv loops; broadcast
// f32x2 operands load directly via LDS.128/LDS.64), tanh.approx.f32 for
// conv1/conv2 activations (accurate tanh kept for the network head),
// 1 image/CTA so all stage guards are single-pass (<224). Constant-memory
// weights (R10), f32x2 FMA, 5 CTAs/SM.
// (Resubmission after infra failure; guards/bounds/alignment/capture audited.)
// ---------------------------------------------------------------------------

#define MAIN_THREADS 224
typedef unsigned long long u64;

// Staging (written by prep_kernel), then copied into __constant__.
__device__ float g_w1s[600];        // conv1 repacked [(c,ky,kx)][8ch pad]
__device__ float g_k2s[400];        // conv2 channel-summed [tap][16ch]
__device__ float g_k3sT[25 * 120];  // conv3 channel-summed, transposed [i][o]

// Constant tables (separate cache port; zero L1 wavefronts).
__constant__ __align__(16) ulonglong2 c_w1x[150];  // 75 taps x 8 floats
__constant__ __align__(16) ulonglong2 c_k2x[100];  // 25 taps x 16 floats

__device__ __forceinline__ u64 pack2(float lo, float hi) {
    u64 r; asm("mov.b64 %0, {%1,%2};" : "=l"(r) : "f"(lo), "f"(hi)); return r;
}
__device__ __forceinline__ void unpack2(u64 v, float& lo, float& hi) {
    asm("mov.b64 {%0,%1}, %2;" : "=f"(lo), "=f"(hi) : "l"(v));
}
__device__ __forceinline__ u64 ffma2(u64 a, u64 b, u64 c) {
    u64 d; asm("fma.rn.f32x2 %0, %1, %2, %3;" : "=l"(d) : "l"(a), "l"(b), "l"(c));
    return d;
}
// Accurate-ish tanh (head stages).
__device__ __forceinline__ float ftanh(float x) {
    x = fminf(fmaxf(x, -15.0f), 15.0f);
    float e = __expf(2.0f * x);
    return __fdividef(e - 1.0f, e + 1.0f);
}
// HW tanh (MUFU), ~5e-4 abs err — used deep in the conv stack only.
__device__ __forceinline__ float ftanh_hw(float x) {
    float y; asm("tanh.approx.f32 %0, %1;" : "=f"(y) : "f"(x)); return y;
}

__global__ void prep_kernel(const float* __restrict__ k1,
                            const float* __restrict__ k2,
                            const float* __restrict__ k3) {
    int t = threadIdx.x;
    // conv1: k1 [o][c][ky][kx] -> g_w1s[((c*5+ky)*5+kx)*8 + o], o>=6 zero.
    if (t < 600) {
        int ch = t & 7;
        int rest = t >> 3;                 // (c*5+ky)*5+kx
        int c = rest / 25, ky = (rest % 25) / 5, kx = rest % 5;
        g_w1s[t] = (ch < 6) ? k1[((ch * 3 + c) * 5 + ky) * 5 + kx] : 0.f;
    }
    // conv2: channel-sum, transposed [tap][16ch].
    if (t < 400) {
        int i = t / 16, o = t % 16;
        float s = 0.f;
#pragma unroll
        for (int c = 0; c < 6; c++) s += k2[(o * 6 + c) * 25 + i];
        g_k2s[t] = s;
    }
    // conv3: channel-sum, transposed [i][o].
    for (int idx = t; idx < 3000; idx += blockDim.x) {
        int i = idx / 120, o = idx % 120;
        float s = 0.f;
#pragma unroll
        for (int c = 0; c < 16; c++) s += k3[(o * 16 + c) * 25 + i];
        g_k3sT[idx] = s;
    }
}

__global__ __launch_bounds__(MAIN_THREADS, 5)
void lenet_fused_kernel(const float* __restrict__ x,
                        const float* __restrict__ W1,
                        const float* __restrict__ b1,
                        const float* __restrict__ W2,
                        const float* __restrict__ b2,
                        float* __restrict__ out,
                        int batch) {
    // 1 image per CTA. Image stored as DUPLICATED pairs: each value v at
    // column cx occupies floats [2cx]=[2cx+1]=v. Row = 72 floats (288B,
    // 16B-aligned, non-pow2 multiple of bank width).
    __shared__ __align__(16) float s_imgd[3 * 32 * 72];  // 27648B
    __shared__ float s_m1[28 * 28];                      // conv1 mean map
    __shared__ __align__(16) float s_p1d[14 * 36];       // pool1, dup pairs
    __shared__ float s_m2[100];                          // conv2 tanh-sums
    __shared__ float s_p2[25];
    __shared__ float s_h3[120];
    __shared__ float s_f[84];

    const int tid = threadIdx.x;
    const int img = blockIdx.x;
    if (img >= batch) return;
    const float* xi = x + (size_t)img * 3072;

    // ---- stage 0: load image into duplicated SMEM layout ----
    for (int i = tid; i < 3072; i += MAIN_THREADS) {
        int c = i >> 10;
        int y = (i >> 5) & 31;
        int xc = i & 31;
        float v = xi[i];
        *reinterpret_cast<u64*>(&s_imgd[c * 2304 + y * 72 + 2 * xc]) =
            pack2(v, v);
    }
    __syncthreads();

    // ---- stage 1: conv1 (3->6) + tanh + channel mean -> s_m1 ----
    // 196 tasks: 1 row x 4 cols. Broadcast operands come pre-paired from
    // s_imgd (4x LDS.128 per row-window, no packs). Weights from constant.
    if (tid < 196) {
        int row = tid / 7;             // 0..27
        int x0 = (tid % 7) * 4;

        u64 acc[3][4];
#pragma unroll
        for (int p = 0; p < 3; p++)
#pragma unroll
            for (int j = 0; j < 4; j++) acc[p][j] = 0ull;

#pragma unroll 1
        for (int c = 0; c < 3; c++) {
            const float* cb = s_imgd + c * 2304;
#pragma unroll
            for (int ky = 0; ky < 5; ky++) {
                const float* rp = cb + (row + ky) * 72 + 2 * x0;
                ulonglong2 q0 = *reinterpret_cast<const ulonglong2*>(rp);
                ulonglong2 q1 = *reinterpret_cast<const ulonglong2*>(rp + 4);
                ulonglong2 q2 = *reinterpret_cast<const ulonglong2*>(rp + 8);
                ulonglong2 q3 = *reinterpret_cast<const ulonglong2*>(rp + 12);
                u64 r8[8] = {q0.x, q0.y, q1.x, q1.y, q2.x, q2.y, q3.x, q3.y};

                int tapB = (c * 5 + ky) * 5;
#pragma unroll
                for (int kx = 0; kx < 5; kx++) {
                    ulonglong2 wAB = c_w1x[(tapB + kx) * 2];
                    u64 wC = c_w1x[(tapB + kx) * 2 + 1].x;
#pragma unroll
                    for (int j = 0; j < 4; j++) {
                        acc[0][j] = ffma2(r8[kx + j], wAB.x, acc[0][j]);
                        acc[1][j] = ffma2(r8[kx + j], wAB.y, acc[1][j]);
                        acc[2][j] = ffma2(r8[kx + j], wC,    acc[2][j]);
                    }
                }
            }
        }
        float m[4] = {0.f, 0.f, 0.f, 0.f};
#pragma unroll
        for (int p = 0; p < 3; p++)
#pragma unroll
            for (int j = 0; j < 4; j++) {
                float a0, a1;
                unpack2(acc[p][j], a0, a1);
                m[j] += ftanh_hw(a0) + ftanh_hw(a1);
            }
#pragma unroll
        for (int j = 0; j < 4; j++)
            s_m1[row * 28 + x0 + j] = m[j] * (1.0f / 6.0f);
    }
    __syncthreads();

    // ---- stage 2: 2x2 avg pool -> s_p1d (duplicated pairs) ----
    if (tid < 196) {
        int y = tid / 14, xx = tid % 14;
        const float* a = s_m1 + (2 * y) * 28 + 2 * xx;
        float q = 0.25f * (a[0] + a[1] + a[28] + a[29]);
        *reinterpret_cast<u64*>(&s_p1d[y * 36 + 2 * xx]) = pack2(q, q);
    }
    __syncthreads();

    // ---- stage 3: conv2sum (1->16) + tanh, 1 px/thread ----
    if (tid < 100) {
        int y = tid / 10, xx = tid % 10;
        u64 acc[8];
#pragma unroll
        for (int p = 0; p < 8; p++) acc[p] = 0ull;
#pragma unroll
        for (int ky = 0; ky < 5; ky++) {
            const float* rp = s_p1d + (y + ky) * 36 + 2 * xx;
            u64 rb[5];
#pragma unroll
            for (int k = 0; k < 5; k++)
                rb[k] = *reinterpret_cast<const u64*>(rp + 2 * k);
#pragma unroll
            for (int kx = 0; kx < 5; kx++) {
                int i = ky * 5 + kx;
                ulonglong2 w0 = c_k2x[i * 4];
                ulonglong2 w1 = c_k2x[i * 4 + 1];
                ulonglong2 w2 = c_k2x[i * 4 + 2];
                ulonglong2 w3 = c_k2x[i * 4 + 3];
                acc[0] = ffma2(rb[kx], w0.x, acc[0]);
                acc[1] = ffma2(rb[kx], w0.y, acc[1]);
                acc[2] = ffma2(rb[kx], w1.x, acc[2]);
                acc[3] = ffma2(rb[kx], w1.y, acc[3]);
                acc[4] = ffma2(rb[kx], w2.x, acc[4]);
                acc[5] = ffma2(rb[kx], w2.y, acc[5]);
                acc[6] = ffma2(rb[kx], w3.x, acc[6]);
                acc[7] = ffma2(rb[kx], w3.y, acc[7]);
            }
        }
        float s = 0.f;
#pragma unroll
        for (int p = 0; p < 8; p++) {
            float a0, a1;
            unpack2(acc[p], a0, a1);
            s += ftanh_hw(a0) + ftanh_hw(a1);
        }
        s_m2[y * 10 + xx] = s;   // raw sum of 16 tanh
    }
    __syncthreads();

    // ---- stage 4: channel-mean(/16) + 2x2 pool -> s_p2[25] ----
    if (tid < 25) {
        int y = tid / 5, xx = tid % 5;
        float s = s_m2[(2 * y) * 10 + 2 * xx] + s_m2[(2 * y) * 10 + 2 * xx + 1] +
                  s_m2[(2 * y + 1) * 10 + 2 * xx] +
                  s_m2[(2 * y + 1) * 10 + 2 * xx + 1];
        s_p2[tid] = s * (0.25f / 16.0f);
    }
    __syncthreads();

    // ---- stage 5: k3sum dot (25->120) + tanh -> s_h3 ----
    if (tid < 120) {
        float a = 0.f;
#pragma unroll
        for (int i = 0; i < 25; i++) a += s_p2[i] * g_k3sT[i * 120 + tid];
        s_h3[tid] = ftanh(a);
    }
    __syncthreads();

    // ---- stage 6: fc1 (120->84) + tanh ----
    if (tid < 84) {
        float a = b1[tid];
#pragma unroll 8
        for (int i = 0; i < 120; i++) a += s_h3[i] * W1[i * 84 + tid];
        s_f[tid] = ftanh(a);
    }
    __syncthreads();

    // ---- stage 7: fc2 (84->10) ----
    if (tid < 10) {
        float a = b2[tid];
#pragma unroll
        for (int j = 0; j < 84; j++) a += s_f[j] * W2[j * 10 + tid];
        out[(size_t)img * 10 + tid] = a;
    }
}

extern "C" void kernel_launch(void* const* d_in, const int* in_sizes, int n_in,
                              void* d_out, int out_size) {
    const float* x  = (const float*)d_in[0];   // [B,3,32,32]
    const float* k1 = (const float*)d_in[1];   // [6,3,5,5]
    const float* k2 = (const float*)d_in[2];   // [16,6,5,5]
    const float* k3 = (const float*)d_in[3];   // [120,16,5,5]
    const float* W1 = (const float*)d_in[4];   // [120,84]
    const float* b1 = (const float*)d_in[5];   // [84]
    const float* W2 = (const float*)d_in[6];   // [84,10]
    const float* b2 = (const float*)d_in[7];   // [10]
    float* out = (float*)d_out;                // [B,10]

    int batch = in_sizes[0] / 3072;

    prep_kernel<<<1, 640>>>(k1, k2, k3);

    // Publish staged weight tables to __constant__ (D2D async memcpys —
    // graph-capturable memcpy-to-symbol nodes).
    void* p_w1s = nullptr;
    void* p_k2s = nullptr;
    cudaGetSymbolAddress(&p_w1s, g_w1s);
    cudaGetSymbolAddress(&p_k2s, g_k2s);
    cudaMemcpyToSymbolAsync(c_w1x, p_w1s, 600 * sizeof(float), 0,
                            cudaMemcpyDeviceToDevice, 0);
    cudaMemcpyToSymbolAsync(c_k2x, p_k2s, 400 * sizeof(float), 0,
                            cudaMemcpyDeviceToDevice, 0);

    lenet_fused_kernel<<<batch, MAIN_THREADS>>>(x, W1, b1, W2, b2, out, batch);
}

// round 13
// speedup vs baseline: 1.6009x; 1.6009x over previous
#include <cuda_runtime.h>

// ---------------------------------------------------------------------------
// CustomCNN (LeNet-like), batch 8192, sm_100a.
// Channel-collapse identity => conv1(3->6)+tanh+mean+pool -> conv2sum(1->16)
// +tanh+mean+pool -> 25->120 dot -> fc1 -> fc2.
// R13 = R10 structure (2 images/CTA, constant-memory weights, f32x2 FMA,
// 5 CTAs/SM — best measured: 180.4us) + tanh.approx.f32 for conv1/conv2
// activations (validated in R12: rel_err ~1e-5). Head keeps accurate tanh.
// ---------------------------------------------------------------------------

#define MAIN_THREADS 224
typedef unsigned long long u64;

// Staging (written by prep_kernel), then copied into __constant__.
__device__ float g_w1s[600];        // conv1 repacked [(c,ky,kx)][8ch pad]
__device__ float g_k2s[400];        // conv2 channel-summed [tap][16ch]
__device__ float g_k3sT[25 * 120];  // conv3 channel-summed, transposed [i][o]

// Constant tables (separate cache port; zero L1 wavefronts).
__constant__ __align__(16) ulonglong2 c_w1x[150];  // 75 taps x 8 floats
__constant__ __align__(16) ulonglong2 c_k2x[100];  // 25 taps x 16 floats

__device__ __forceinline__ u64 pack2(float lo, float hi) {
    u64 r; asm("mov.b64 %0, {%1,%2};" : "=l"(r) : "f"(lo), "f"(hi)); return r;
}
__device__ __forceinline__ void unpack2(u64 v, float& lo, float& hi) {
    asm("mov.b64 {%0,%1}, %2;" : "=f"(lo), "=f"(hi) : "l"(v));
}
__device__ __forceinline__ u64 ffma2(u64 a, u64 b, u64 c) {
    u64 d; asm("fma.rn.f32x2 %0, %1, %2, %3;" : "=l"(d) : "l"(a), "l"(b), "l"(c));
    return d;
}
// Accurate-ish tanh (head stages 5-6).
__device__ __forceinline__ float ftanh(float x) {
    x = fminf(fmaxf(x, -15.0f), 15.0f);
    float e = __expf(2.0f * x);
    return __fdividef(e - 1.0f, e + 1.0f);
}
// HW tanh (MUFU, 1 instr) — conv stack only; validated rel_err ~1e-5 in R12.
__device__ __forceinline__ float ftanh_hw(float x) {
    float y; asm("tanh.approx.f32 %0, %1;" : "=f"(y) : "f"(x)); return y;
}

__global__ void prep_kernel(const float* __restrict__ k1,
                            const float* __restrict__ k2,
                            const float* __restrict__ k3) {
    int t = threadIdx.x;
    // conv1: k1 [o][c][ky][kx] -> g_w1s[((c*5+ky)*5+kx)*8 + o], o>=6 zero.
    if (t < 600) {
        int ch = t & 7;
        int rest = t >> 3;                 // (c*5+ky)*5+kx
        int c = rest / 25, ky = (rest % 25) / 5, kx = rest % 5;
        g_w1s[t] = (ch < 6) ? k1[((ch * 3 + c) * 5 + ky) * 5 + kx] : 0.f;
    }
    // conv2: channel-sum, transposed [tap][16ch].
    if (t < 400) {
        int i = t / 16, o = t % 16;
        float s = 0.f;
#pragma unroll
        for (int c = 0; c < 6; c++) s += k2[(o * 6 + c) * 25 + i];
        g_k2s[t] = s;
    }
    // conv3: channel-sum, transposed [i][o].
    for (int idx = t; idx < 3000; idx += blockDim.x) {
        int i = idx / 120, o = idx % 120;
        float s = 0.f;
#pragma unroll
        for (int c = 0; c < 16; c++) s += k3[(o * 16 + c) * 25 + i];
        g_k3sT[idx] = s;
    }
}

__global__ __launch_bounds__(MAIN_THREADS, 5)
void lenet_fused_kernel(const float* __restrict__ x,
                        const float* __restrict__ W1,
                        const float* __restrict__ b1,
                        const float* __restrict__ W2,
                        const float* __restrict__ b2,
                        float* __restrict__ out,
                        int batch) {
    // 2 images per CTA. Image rows padded to 36 floats (16B-aligned rows).
    __shared__ __align__(16) float s_img[2 * 3 * 32 * 36];  // 6912
    __shared__ float s_m1[2 * 28 * 28];                     // 1568
    __shared__ float s_p1[2 * 14 * 14];                     // 392
    __shared__ float s_m2[2 * 100];                         // conv2 tanh-sums
    __shared__ float s_p2[2 * 25];
    __shared__ float s_h3[2 * 120];
    __shared__ float s_f[2 * 84];

    const int tid = threadIdx.x;
    const int base = blockIdx.x * 2;
    const int nimg = (base + 2 <= batch) ? 2 : (batch - base);

    // ---- stage 0: load images (row-padded) into SMEM ----
    for (int v = 0; v < nimg; v++) {
        const float* xi = x + (size_t)(base + v) * 3072;
        float* si = s_img + v * 3456;
        for (int i = tid; i < 3072; i += MAIN_THREADS) {
            int c = i >> 10;
            int y = (i >> 5) & 31;
            int xc = i & 31;
            si[c * (32 * 36) + y * 36 + xc] = xi[i];
        }
    }
    __syncthreads();

    // ---- stage 1: conv1 (3->6) + tanh + channel mean -> s_m1 ----
    // 392 tasks (2 images x 28 rows x 7 col-segs), 2 strided passes.
    // Weights from __constant__ (LDC), images from SMEM.
#pragma unroll 1
    for (int pass = 0; pass < 2; pass++) {
        int q = tid + pass * MAIN_THREADS;
        if (q < 392) {
            int v = q / 196;
            if (v < nimg) {
                int t = q % 196;
                int row = t / 7;             // 0..27
                int x0 = (t % 7) * 4;
                const float* img = s_img + v * 3456;

                u64 acc[3][4];
#pragma unroll
                for (int p = 0; p < 3; p++)
#pragma unroll
                    for (int j = 0; j < 4; j++) acc[p][j] = 0ull;

#pragma unroll 1
                for (int c = 0; c < 3; c++) {
                    const float* cb = img + c * 1152;
#pragma unroll
                    for (int ky = 0; ky < 5; ky++) {
                        const float* rp = cb + (row + ky) * 36 + x0;
                        float4 a = *reinterpret_cast<const float4*>(rp);
                        float4 b = *reinterpret_cast<const float4*>(rp + 4);
                        u64 r8[8];
                        r8[0] = pack2(a.x, a.x); r8[1] = pack2(a.y, a.y);
                        r8[2] = pack2(a.z, a.z); r8[3] = pack2(a.w, a.w);
                        r8[4] = pack2(b.x, b.x); r8[5] = pack2(b.y, b.y);
                        r8[6] = pack2(b.z, b.z); r8[7] = pack2(b.w, b.w);

                        int tapB = (c * 5 + ky) * 5;
#pragma unroll
                        for (int kx = 0; kx < 5; kx++) {
                            ulonglong2 wAB = c_w1x[(tapB + kx) * 2];
                            u64 wC = c_w1x[(tapB + kx) * 2 + 1].x;
#pragma unroll
                            for (int j = 0; j < 4; j++) {
                                acc[0][j] = ffma2(r8[kx + j], wAB.x, acc[0][j]);
                                acc[1][j] = ffma2(r8[kx + j], wAB.y, acc[1][j]);
                                acc[2][j] = ffma2(r8[kx + j], wC,    acc[2][j]);
                            }
                        }
                    }
                }
                float m[4] = {0.f, 0.f, 0.f, 0.f};
#pragma unroll
                for (int p = 0; p < 3; p++)
#pragma unroll
                    for (int j = 0; j < 4; j++) {
                        float a0, a1;
                        unpack2(acc[p][j], a0, a1);
                        m[j] += ftanh_hw(a0) + ftanh_hw(a1);
                    }
#pragma unroll
                for (int j = 0; j < 4; j++)
                    s_m1[v * 784 + row * 28 + x0 + j] = m[j] * (1.0f / 6.0f);
            }
        }
    }
    __syncthreads();

    // ---- stage 2: 2x2 avg pool -> s_p1 ----
    if (tid < 196) {
        int y = tid / 14, xx = tid % 14;
        for (int v = 0; v < nimg; v++) {
            const float* a = s_m1 + v * 784 + (2 * y) * 28 + 2 * xx;
            s_p1[v * 196 + tid] = 0.25f * (a[0] + a[1] + a[28] + a[29]);
        }
    }
    __syncthreads();

    // ---- stage 3: conv2sum (1->16) + tanh, 1 px/thread, constant weights ---
    if (tid < 200) {
        int v = tid / 100;
        if (v < nimg) {
            int pix = tid % 100;
            int y = pix / 10, xx = pix % 10;
            const float* p1 = s_p1 + v * 196;
            u64 acc[8];
#pragma unroll
            for (int p = 0; p < 8; p++) acc[p] = 0ull;
#pragma unroll
            for (int ky = 0; ky < 5; ky++) {
                const float* rp = p1 + (y + ky) * 14 + xx;
                u64 rb[5];
#pragma unroll
                for (int k = 0; k < 5; k++) {
                    float val = rp[k];
                    rb[k] = pack2(val, val);
                }
#pragma unroll
                for (int kx = 0; kx < 5; kx++) {
                    int i = ky * 5 + kx;
                    ulonglong2 w0 = c_k2x[i * 4];
                    ulonglong2 w1 = c_k2x[i * 4 + 1];
                    ulonglong2 w2 = c_k2x[i * 4 + 2];
                    ulonglong2 w3 = c_k2x[i * 4 + 3];
                    acc[0] = ffma2(rb[kx], w0.x, acc[0]);
                    acc[1] = ffma2(rb[kx], w0.y, acc[1]);
                    acc[2] = ffma2(rb[kx], w1.x, acc[2]);
                    acc[3] = ffma2(rb[kx], w1.y, acc[3]);
                    acc[4] = ffma2(rb[kx], w2.x, acc[4]);
                    acc[5] = ffma2(rb[kx], w2.y, acc[5]);
                    acc[6] = ffma2(rb[kx], w3.x, acc[6]);
                    acc[7] = ffma2(rb[kx], w3.y, acc[7]);
                }
            }
            float s = 0.f;
#pragma unroll
            for (int p = 0; p < 8; p++) {
                float a0, a1;
                unpack2(acc[p], a0, a1);
                s += ftanh_hw(a0) + ftanh_hw(a1);
            }
            s_m2[v * 100 + pix] = s;   // raw sum of 16 tanh
        }
    }
    __syncthreads();

    // ---- stage 4: channel-mean(/16) + 2x2 pool -> s_p2[25] ----
    if (tid < 50) {
        int v = tid / 25;
        if (v < nimg) {
            int t = tid % 25;
            int y = t / 5, xx = t % 5;
            const float* mp = s_m2 + v * 100;
            float s = mp[(2 * y) * 10 + 2 * xx] + mp[(2 * y) * 10 + 2 * xx + 1] +
                      mp[(2 * y + 1) * 10 + 2 * xx] + mp[(2 * y + 1) * 10 + 2 * xx + 1];
            s_p2[v * 25 + t] = s * (0.25f / 16.0f);
        }
    }
    __syncthreads();

    // ---- stage 5: k3sum dot (25->120) + tanh -> s_h3 ----
    // 240 tasks on 224 threads: strided loop.
    for (int t = tid; t < 240; t += MAIN_THREADS) {
        int v = t / 120;
        if (v < nimg) {
            int o = t % 120;
            const float* p2 = s_p2 + v * 25;
            float a = 0.f;
#pragma unroll
            for (int i = 0; i < 25; i++) a += p2[i] * g_k3sT[i * 120 + o];
            s_h3[v * 120 + o] = ftanh(a);
        }
    }
    __syncthreads();

    // ---- stage 6: fc1 (120->84) + tanh ----
    if (tid < 168) {
        int v = tid / 84;
        if (v < nimg) {
            int o = tid % 84;
            const float* h3 = s_h3 + v * 120;
            float a = b1[o];
#pragma unroll 8
            for (int i = 0; i < 120; i++) a += h3[i] * W1[i * 84 + o];
            s_f[v * 84 + o] = ftanh(a);
        }
    }
    __syncthreads();

    // ---- stage 7: fc2 (84->10) ----
    if (tid < 20) {
        int v = tid / 10;
        if (v < nimg) {
            int o = tid % 10;
            const float* f = s_f + v * 84;
            float a = b2[o];
#pragma unroll
            for (int j = 0; j < 84; j++) a += f[j] * W2[j * 10 + o];
            out[(size_t)(base + v) * 10 + o] = a;
        }
    }
}

extern "C" void kernel_launch(void* const* d_in, const int* in_sizes, int n_in,
                              void* d_out, int out_size) {
    const float* x  = (const float*)d_in[0];   // [B,3,32,32]
    const float* k1 = (const float*)d_in[1];   // [6,3,5,5]
    const float* k2 = (const float*)d_in[2];   // [16,6,5,5]
    const float* k3 = (const float*)d_in[3];   // [120,16,5,5]
    const float* W1 = (const float*)d_in[4];   // [120,84]
    const float* b1 = (const float*)d_in[5];   // [84]
    const float* W2 = (const float*)d_in[6];   // [84,10]
    const float* b2 = (const float*)d_in[7];   // [10]
    float* out = (float*)d_out;                // [B,10]

    int batch = in_sizes[0] / 3072;
    int blocks = (batch + 1) / 2;

    prep_kernel<<<1, 640>>>(k1, k2, k3);

    // Publish staged weight tables to __constant__ (D2D async memcpys —
    // graph-capturable memcpy-to-symbol nodes).
    void* p_w1s = nullptr;
    void* p_k2s = nullptr;
    cudaGetSymbolAddress(&p_w1s, g_w1s);
    cudaGetSymbolAddress(&p_k2s, g_k2s);
    cudaMemcpyToSymbolAsync(c_w1x, p_w1s, 600 * sizeof(float), 0,
                            cudaMemcpyDeviceToDevice, 0);
    cudaMemcpyToSymbolAsync(c_k2x, p_k2s, 400 * sizeof(float), 0,
                            cudaMemcpyDeviceToDevice, 0);

    lenet_fused_kernel<<<blocks, MAIN_THREADS>>>(x, W1, b1, W2, b2, out, batch);
}